// round 1
// baseline (speedup 1.0000x reference)
#include <cuda_runtime.h>
#include <math.h>
#include <stdint.h>

// ---------------- problem constants ----------------
#define B    128
#define NP   1024
#define NN   (B*NP)        // 131072 nodes
#define H    128
#define C    10
#define DEG  16
#define NE   (NN*DEG)      // 2097152 edges
#define K1   820
#define K2   656
#define K3   525

// ---------------- device scratch (no mallocs allowed) ----------------
__device__ float g_x[(size_t)NN*H];     // current node features
__device__ float g_mean[(size_t)NN*H];  // aggregated mean
__device__ float g_h[(size_t)NN*H];     // SAGE+ReLU output
__device__ float g_score[NN];
__device__ unsigned char g_nm[NN];      // node alive mask
__device__ int  g_liveA[NN];            // per-graph live lists (stride NP)
__device__ int  g_liveB[NN];
__device__ int  g_deg[NN];
__device__ int  g_rowptr[NN+1];
__device__ int  g_cursor[NN];
__device__ int  g_cols[NE];
__device__ int  g_bs[128];
__device__ float g_invwp;

// ---------------- setup kernels ----------------
__global__ void k_copy_x(const float* __restrict__ x) {
    size_t i = (size_t)blockIdx.x*blockDim.x + threadIdx.x;   // in float4 units
    ((float4*)g_x)[i] = ((const float4*)x)[i];
}

__global__ void k_init() {
    int i = blockIdx.x*blockDim.x + threadIdx.x;
    if (i < NN) { g_nm[i] = 1; g_deg[i] = 0; }
}

__global__ void k_count(const int* __restrict__ dst) {
    int e = blockIdx.x*blockDim.x + threadIdx.x;
    if (e < NE) atomicAdd(&g_deg[dst[e]], 1);
}

// exclusive scan of g_deg -> g_rowptr (N = 128 blocks x 1024)
__global__ void k_scan1() {
    __shared__ int s[1024];
    int i = blockIdx.x*1024 + threadIdx.x;
    int v = g_deg[i];
    s[threadIdx.x] = v;
    __syncthreads();
    for (int off = 1; off < 1024; off <<= 1) {
        int t = (threadIdx.x >= off) ? s[threadIdx.x - off] : 0;
        __syncthreads();
        s[threadIdx.x] += t;
        __syncthreads();
    }
    g_rowptr[i] = s[threadIdx.x] - v;                 // block-local exclusive
    if (threadIdx.x == 1023) g_bs[blockIdx.x] = s[1023];
}
__global__ void k_scan2() {      // 1 block, 128 threads
    __shared__ int s[128];
    int v = g_bs[threadIdx.x];
    s[threadIdx.x] = v;
    __syncthreads();
    for (int off = 1; off < 128; off <<= 1) {
        int t = (threadIdx.x >= off) ? s[threadIdx.x - off] : 0;
        __syncthreads();
        s[threadIdx.x] += t;
        __syncthreads();
    }
    g_bs[threadIdx.x] = s[threadIdx.x] - v;
}
__global__ void k_scan3() {
    int i = blockIdx.x*1024 + threadIdx.x;
    int v = g_rowptr[i] + g_bs[blockIdx.x];
    g_rowptr[i] = v;
    g_cursor[i] = v;
    if (i == 0) g_rowptr[NN] = NE;
}

__global__ void k_fill(const int* __restrict__ src, const int* __restrict__ dst) {
    int e = blockIdx.x*blockDim.x + threadIdx.x;
    if (e < NE) {
        int pos = atomicAdd(&g_cursor[dst[e]], 1);
        g_cols[pos] = src[e];
    }
}

__global__ void k_wpnorm(const float* __restrict__ wp) {
    __shared__ float s[128];
    float v = wp[threadIdx.x];
    s[threadIdx.x] = v*v;
    __syncthreads();
    for (int o = 64; o > 0; o >>= 1) {
        if (threadIdx.x < o) s[threadIdx.x] += s[threadIdx.x + o];
        __syncthreads();
    }
    if (threadIdx.x == 0) g_invwp = 1.0f/(sqrtf(s[0]) + 1e-16f);
}

// ---------------- SAGE mean aggregation: one warp per live dst ----------------
__global__ void k_agg(int livesel, int kkprev, int M) {
    const int* live = (livesel == 1) ? g_liveA : (livesel == 2) ? g_liveB : nullptr;
    int w = (blockIdx.x*blockDim.x + threadIdx.x) >> 5;
    int lane = threadIdx.x & 31;
    if (w >= M) return;
    int node;
    if (live) { int b = w / kkprev; node = live[b*NP + (w - b*kkprev)]; }
    else node = w;
    int s = g_rowptr[node], e = g_rowptr[node+1];
    float4 acc = make_float4(0.f, 0.f, 0.f, 0.f);
    int cnt = 0;
    for (int p = s; p < e; p++) {
        int j = g_cols[p];
        if (g_nm[j]) {
            cnt++;
            float4 v = ((const float4*)(g_x + (size_t)j*H))[lane];
            acc.x += v.x; acc.y += v.y; acc.z += v.z; acc.w += v.w;
        }
    }
    float inv = 1.0f / (float)max(cnt, 1);
    float4 o = make_float4(acc.x*inv, acc.y*inv, acc.z*inv, acc.w*inv);
    ((float4*)(g_mean + (size_t)node*H))[lane] = o;
}

// ---------------- fused dual GEMM: h = relu(mean@Wl^T + x@Wr^T + bl), + score ----------------
__global__ __launch_bounds__(256) void k_gemm(int livesel, int kkprev, int M,
        const float* __restrict__ Wl, const float* __restrict__ Wr,
        const float* __restrict__ bl, const float* __restrict__ wp) {
    const int* live = (livesel == 1) ? g_liveA : (livesel == 2) ? g_liveB : nullptr;
    __shared__ float As[16][132];
    __shared__ float Ws[16][132];
    __shared__ float sb[128];
    __shared__ float swp[128];
    __shared__ float ssc[128];
    __shared__ int snode[128];

    int tid = threadIdx.x;
    int tx = tid & 15, ty = tid >> 4;
    int rowbase = blockIdx.x * 128;

    if (tid < 128) {
        int r = rowbase + tid;
        int node = -1;
        if (r < M) {
            if (live) { int b = r / kkprev; node = live[b*NP + (r - b*kkprev)]; }
            else node = r;
        }
        snode[tid] = node;
        sb[tid]  = bl[tid];
        swp[tid] = wp[tid] * g_invwp;
        ssc[tid] = 0.f;
    }
    __syncthreads();

    float acc[8][8];
    #pragma unroll
    for (int u = 0; u < 8; u++)
        #pragma unroll
        for (int v = 0; v < 8; v++) acc[u][v] = 0.f;

    for (int pass = 0; pass < 2; pass++) {
        const float* A = pass ? g_x : g_mean;
        const float* W = pass ? Wr  : Wl;
        for (int kb = 0; kb < 128; kb += 16) {
            {   // A chunk: As[k][row]
                int r = tid >> 1, koff = (tid & 1) * 8;
                int node = snode[r];
                float4 v0 = make_float4(0,0,0,0), v1 = make_float4(0,0,0,0);
                if (node >= 0) {
                    const float* p = A + (size_t)node*H + kb + koff;
                    v0 = *(const float4*)p;
                    v1 = *(const float4*)(p + 4);
                }
                As[koff+0][r] = v0.x; As[koff+1][r] = v0.y;
                As[koff+2][r] = v0.z; As[koff+3][r] = v0.w;
                As[koff+4][r] = v1.x; As[koff+5][r] = v1.y;
                As[koff+6][r] = v1.z; As[koff+7][r] = v1.w;
            }
            {   // W chunk: Ws[k][col] = W[c*128 + kb + k]
                int c = tid >> 1, koff = (tid & 1) * 8;
                const float* p = W + (size_t)c*H + kb + koff;
                float4 v0 = *(const float4*)p;
                float4 v1 = *(const float4*)(p + 4);
                Ws[koff+0][c] = v0.x; Ws[koff+1][c] = v0.y;
                Ws[koff+2][c] = v0.z; Ws[koff+3][c] = v0.w;
                Ws[koff+4][c] = v1.x; Ws[koff+5][c] = v1.y;
                Ws[koff+6][c] = v1.z; Ws[koff+7][c] = v1.w;
            }
            __syncthreads();
            #pragma unroll
            for (int k = 0; k < 16; k++) {
                float a[8], bb[8];
                #pragma unroll
                for (int u = 0; u < 8; u++) a[u]  = As[k][ty*8 + u];
                #pragma unroll
                for (int v = 0; v < 8; v++) bb[v] = Ws[k][tx*8 + v];
                #pragma unroll
                for (int u = 0; u < 8; u++)
                    #pragma unroll
                    for (int v = 0; v < 8; v++)
                        acc[u][v] += a[u]*bb[v];
            }
            __syncthreads();
        }
    }

    // epilogue: bias + relu, write h, accumulate score = h . wp_normalized
    float part[8];
    #pragma unroll
    for (int u = 0; u < 8; u++) part[u] = 0.f;
    #pragma unroll
    for (int u = 0; u < 8; u++) {
        int r = ty*8 + u;
        int node = snode[r];
        if (node < 0) continue;
        float4 o0, o1;
        float* hp = g_h + (size_t)node*H + tx*8;
        float hv[8];
        #pragma unroll
        for (int v = 0; v < 8; v++) {
            int c = tx*8 + v;
            hv[v] = fmaxf(acc[u][v] + sb[c], 0.f);
            part[u] += hv[v] * swp[c];
        }
        o0 = make_float4(hv[0], hv[1], hv[2], hv[3]);
        o1 = make_float4(hv[4], hv[5], hv[6], hv[7]);
        *(float4*)hp       = o0;
        *(float4*)(hp + 4) = o1;
    }
    #pragma unroll
    for (int u = 0; u < 8; u++) atomicAdd(&ssc[ty*8 + u], part[u]);
    __syncthreads();
    if (tid < 128) {
        int node = snode[tid];
        if (node >= 0) g_score[node] = ssc[tid];
    }
}

// ---------------- per-graph top-k (exact, tie = lower index), gate x ----------------
__global__ void k_topk(int livesel_in, int mlive, int kk, int livesel_out) {
    const int* live_in = (livesel_in == 1) ? g_liveA : (livesel_in == 2) ? g_liveB : nullptr;
    int* live_out = (livesel_out == 1) ? g_liveA : g_liveB;
    __shared__ unsigned long long keys[1024];
    __shared__ float gates[1024];
    int b = blockIdx.x;
    int tid = threadIdx.x;   // 512 threads

    for (int t = tid; t < 1024; t += 512) {
        unsigned long long key = 0xFFFFFFFFFFFFFFFFULL;
        if (t < mlive) {
            int node = live_in ? live_in[b*NP + t] : (b*NP + t);
            unsigned int p = (unsigned int)(node - b*NP);
            float s = g_score[node];
            unsigned int u = __float_as_uint(s);
            u = (u & 0x80000000u) ? ~u : (u | 0x80000000u);  // ascending-orderable
            key = (((unsigned long long)(~u)) << 32) | p;    // desc score, asc idx
        }
        keys[t] = key;
    }
    __syncthreads();

    for (int k = 2; k <= 1024; k <<= 1) {
        for (int j = k >> 1; j > 0; j >>= 1) {
            for (int t = tid; t < 1024; t += 512) {
                int l = t ^ j;
                if (l > t) {
                    bool asc = ((t & k) == 0);
                    unsigned long long a = keys[t], c2 = keys[l];
                    if ((a > c2) == asc) { keys[t] = c2; keys[l] = a; }
                }
            }
            __syncthreads();
        }
    }

    // clear this graph's mask, then set selected
    for (int t = tid; t < NP; t += 512) g_nm[b*NP + t] = 0;
    __syncthreads();
    for (int s = tid; s < kk; s += 512) {
        unsigned int p = (unsigned int)(keys[s] & 0xFFFFFFFFu);
        int node = b*NP + (int)p;
        g_nm[node] = 1;
        live_out[b*NP + s] = node;
        gates[s] = tanhf(g_score[node]);
    }
    __syncthreads();
    // x[node] = h[node] * tanh(score)   (non-selected stay masked via nm/live lists)
    for (int w = tid; w < kk*32; w += 512) {
        int s = w >> 5, f = w & 31;
        unsigned int p = (unsigned int)(keys[s] & 0xFFFFFFFFu);
        int node = b*NP + (int)p;
        float4 hv = ((const float4*)(g_h + (size_t)node*H))[f];
        float g = gates[s];
        ((float4*)(g_x + (size_t)node*H))[f] =
            make_float4(hv.x*g, hv.y*g, hv.z*g, hv.w*g);
    }
}

// ---------------- mean pool + MLP + log_softmax ----------------
__global__ void k_mlp(int livesel, const float* __restrict__ Wf1, const float* __restrict__ bf1,
                      const float* __restrict__ Wf2, const float* __restrict__ bf2,
                      float* __restrict__ out) {
    const int* live = (livesel == 1) ? g_liveA : g_liveB;
    __shared__ float pooled[128];
    __shared__ float h1[64];
    __shared__ float o10[10];
    int b = blockIdx.x, d = threadIdx.x;   // 128 threads
    float s = 0.f;
    for (int i = 0; i < K3; i++) {
        int node = live[b*NP + i];
        s += g_x[(size_t)node*H + d];
    }
    pooled[d] = s * (1.0f/(float)K3);
    __syncthreads();
    if (d < 64) {
        float a = bf1[d];
        for (int k = 0; k < 128; k++) a += pooled[k] * Wf1[d*128 + k];
        h1[d] = fmaxf(a, 0.f);
    }
    __syncthreads();
    if (d < 10) {
        float a = bf2[d];
        for (int k = 0; k < 64; k++) a += h1[k] * Wf2[d*64 + k];
        o10[d] = a;
    }
    __syncthreads();
    if (d == 0) {
        float m = -1e30f;
        for (int c = 0; c < C; c++) m = fmaxf(m, o10[c]);
        float se = 0.f;
        for (int c = 0; c < C; c++) se += expf(o10[c] - m);
        float lse = m + logf(se);
        for (int c = 0; c < C; c++) out[b*C + c] = o10[c] - lse;
    }
}

// ---------------- launch ----------------
extern "C" void kernel_launch(void* const* d_in, const int* in_sizes, int n_in,
                              void* d_out, int out_size) {
    const float* x   = (const float*)d_in[0];
    const int*   ei  = (const int*)  d_in[1];
    const float* Wl1 = (const float*)d_in[2];
    const float* bl1 = (const float*)d_in[3];
    const float* Wr1 = (const float*)d_in[4];
    const float* wp1 = (const float*)d_in[5];
    const float* Wl2 = (const float*)d_in[6];
    const float* bl2 = (const float*)d_in[7];
    const float* Wr2 = (const float*)d_in[8];
    const float* wp2 = (const float*)d_in[9];
    const float* Wl3 = (const float*)d_in[10];
    const float* bl3 = (const float*)d_in[11];
    const float* Wr3 = (const float*)d_in[12];
    const float* wp3 = (const float*)d_in[13];
    const float* Wf1 = (const float*)d_in[14];
    const float* bf1 = (const float*)d_in[15];
    const float* Wf2 = (const float*)d_in[16];
    const float* bf2 = (const float*)d_in[17];
    float* out = (float*)d_out;

    const int* srcp = ei;
    const int* dstp = ei + NE;

    // stage inputs + CSR build
    k_copy_x<<<(NN*H/4 + 255)/256, 256>>>(x);
    k_init  <<<(NN + 255)/256, 256>>>();
    k_count <<<(NE + 255)/256, 256>>>(dstp);
    k_scan1 <<<128, 1024>>>();
    k_scan2 <<<1, 128>>>();
    k_scan3 <<<128, 1024>>>();
    k_fill  <<<(NE + 255)/256, 256>>>(srcp, dstp);

    // layer 1 (all nodes live)
    k_wpnorm<<<1, 128>>>(wp1);
    k_agg   <<<(NN*32 + 255)/256, 256>>>(0, 1, NN);
    k_gemm  <<<(NN + 127)/128, 256>>>(0, 1, NN, Wl1, Wr1, bl1, wp1);
    k_topk  <<<B, 512>>>(0, NP, K1, 1);

    // layer 2 (live list A, count K1 per graph)
    {
        int M = B * K1;
        k_wpnorm<<<1, 128>>>(wp2);
        k_agg   <<<(M*32 + 255)/256, 256>>>(1, K1, M);
        k_gemm  <<<(M + 127)/128, 256>>>(1, K1, M, Wl2, Wr2, bl2, wp2);
        k_topk  <<<B, 512>>>(1, K1, K2, 2);
    }

    // layer 3 (live list B, count K2 per graph)
    {
        int M = B * K2;
        k_wpnorm<<<1, 128>>>(wp3);
        k_agg   <<<(M*32 + 255)/256, 256>>>(2, K2, M);
        k_gemm  <<<(M + 127)/128, 256>>>(2, K2, M, Wl3, Wr3, bl3, wp3);
        k_topk  <<<B, 512>>>(2, K2, K3, 1);
    }

    // pool + MLP + log_softmax
    k_mlp<<<B, 128>>>(1, Wf1, bf1, Wf2, bf2, out);
}